// round 9
// baseline (speedup 1.0000x reference)
#include <cuda_runtime.h>
#include <cuda_fp16.h>
#include <cmath>

// Problem constants
#define Bq     2
#define Sq     2048
#define Dm     1024
#define NQ     16
#define NKV    4
#define GRP    4
#define DQh    64
#define DVh    64

// Scratch (device globals — no allocation allowed)
__device__ __align__(16) __half g_xnq[Bq*Sq*Dm];
__device__ __align__(16) __half g_xnk[Bq*Sq*Dm];
__device__ __align__(16) __half g_xnv[Bq*Sq*Dm];
__device__ __align__(16) __half g_Wqh[Dm*NQ*DQh];
__device__ __align__(16) __half g_Wkh[Dm*NKV*DQh];
__device__ __align__(16) __half g_Wvh[Dm*NKV*DVh];
__device__ __align__(16) __half g_Woh[NQ*DVh*Dm];
__device__ __align__(16) __half g_Qh[Bq*Sq*NQ*DQh];
__device__ __align__(16) __half g_Kh[Bq*Sq*NKV*DQh];
__device__ __align__(16) __half g_Vh[Bq*Sq*NKV*DVh];
__device__ __align__(16) __half g_Oh[Bq*Sq*NQ*DVh];

// fp16 mma: m16n8k16, f32 accum
#define MMA_F16(c, a, b0, b1)                                                  \
    asm volatile("mma.sync.aligned.m16n8k16.row.col.f32.f16.f16.f32 "          \
                 "{%0,%1,%2,%3},{%4,%5,%6,%7},{%8,%9},{%0,%1,%2,%3};"          \
                 : "+f"((c)[0]), "+f"((c)[1]), "+f"((c)[2]), "+f"((c)[3])      \
                 : "r"((a)[0]), "r"((a)[1]), "r"((a)[2]), "r"((a)[3]),         \
                   "r"(b0), "r"(b1))

__device__ __forceinline__ void ldsmx4(unsigned r[4], unsigned saddr) {
    asm volatile("ldmatrix.sync.aligned.m8n8.x4.shared.b16 {%0,%1,%2,%3}, [%4];"
                 : "=r"(r[0]), "=r"(r[1]), "=r"(r[2]), "=r"(r[3])
                 : "r"(saddr));
}
__device__ __forceinline__ void ldsmx4t(unsigned r[4], unsigned saddr) {
    asm volatile("ldmatrix.sync.aligned.m8n8.x4.trans.shared.b16 {%0,%1,%2,%3}, [%4];"
                 : "=r"(r[0]), "=r"(r[1]), "=r"(r[2]), "=r"(r[3])
                 : "r"(saddr));
}

// A-operand (row-major m16 x k16) ldmatrix lane address; add kk*32 bytes per k16 step
__device__ __forceinline__ unsigned a_frag_addr(const __half* base, int lane,
                                                int r0, int ldm) {
    const __half* p = base + (size_t)(r0 + (lane & 7) + ((lane >> 3) & 1) * 8) * ldm
                           + ((lane >> 4) & 1) * 8;
    return (unsigned)__cvta_generic_to_shared(p);
}
// B-operand, source [n][k] (k contiguous): non-trans ldmatrix (n16 x k16)
__device__ __forceinline__ unsigned bn_frag_addr(const __half* base, int lane,
                                                 int n0, int ldm) {
    const __half* p = base + (size_t)(n0 + (lane & 7) + ((lane >> 4) & 1) * 8) * ldm
                           + ((lane >> 3) & 1) * 8;
    return (unsigned)__cvta_generic_to_shared(p);
}
// B-operand, source [k][n] (n contiguous): trans ldmatrix (k16 x n16)
__device__ __forceinline__ unsigned bt_frag_addr(const __half* base, int lane,
                                                 int k0, int n0, int ldm) {
    const __half* p = base + (size_t)(k0 + (lane & 7) + ((lane >> 3) & 1) * 8) * ldm
                           + n0 + ((lane >> 4) & 1) * 8;
    return (unsigned)__cvta_generic_to_shared(p);
}

__device__ __forceinline__ void cpasync16(unsigned dst, const void* src) {
    asm volatile("cp.async.cg.shared.global [%0], [%1], 16;" :: "r"(dst), "l"(src));
}
#define CP_COMMIT() asm volatile("cp.async.commit_group;")
#define CP_WAIT0()  asm volatile("cp.async.wait_group 0;")
#define CP_WAIT1()  asm volatile("cp.async.wait_group 1;")

__device__ __forceinline__ __half2 f22h(float a, float b) {
    return __floats2half2_rn(a, b);
}
__device__ __forceinline__ unsigned pack_h2(float a, float b) {
    __half2 h = __floats2half2_rn(a, b);
    return *(unsigned*)&h;
}

// ---------------------------------------------------------------------------
// Weight conversion fp32 -> fp16 (one launch, blockIdx.y selects tensor)
// ---------------------------------------------------------------------------
__global__ void w2h_kernel(const float* __restrict__ Wq, const float* __restrict__ Wo,
                           const float* __restrict__ Wk, const float* __restrict__ Wv,
                           __half* q, __half* o_, __half* k, __half* v)
{
    int which = blockIdx.y;
    const float* src = (which == 0) ? Wq : (which == 1) ? Wo : (which == 2) ? Wk : Wv;
    __half* dst      = (which == 0) ? q  : (which == 1) ? o_ : (which == 2) ? k  : v;
    int n = (which < 2) ? Dm * Dm : Dm * NKV * DQh;
    int i = (blockIdx.x * blockDim.x + threadIdx.x) * 4;
    if (i < n) {
        float4 w = *(const float4*)&src[i];
        *(__half2*)&dst[i]     = f22h(w.x, w.y);
        *(__half2*)&dst[i + 2] = f22h(w.z, w.w);
    }
}

// ---------------------------------------------------------------------------
// Fused LayerNorm x3 (fp16 output)
// ---------------------------------------------------------------------------
__global__ void ln3_kernel(const float* __restrict__ xq,
                           const float* __restrict__ xk,
                           const float* __restrict__ xv,
                           const float* __restrict__ gamma,
                           const float* __restrict__ beta,
                           __half* __restrict__ yq,
                           __half* __restrict__ yk,
                           __half* __restrict__ yv)
{
    int row = blockIdx.x;
    int which = blockIdx.y;
    const float* x = (which == 0) ? xq : (which == 1) ? xk : xv;
    __half* y      = (which == 0) ? yq : (which == 1) ? yk : yv;
    int tid = threadIdx.x;
    const float4* xr = (const float4*)(x + (size_t)row * Dm);
    float4 v = xr[tid];
    float s  = v.x + v.y + v.z + v.w;
    float ss = v.x*v.x + v.y*v.y + v.z*v.z + v.w*v.w;
    #pragma unroll
    for (int o = 16; o > 0; o >>= 1) {
        s  += __shfl_down_sync(0xffffffffu, s,  o);
        ss += __shfl_down_sync(0xffffffffu, ss, o);
    }
    __shared__ float as[8], bs[8];
    __shared__ float s_mu, s_inv;
    if ((tid & 31) == 0) { as[tid >> 5] = s; bs[tid >> 5] = ss; }
    __syncthreads();
    if (tid == 0) {
        float S = 0.f, SS = 0.f;
        #pragma unroll
        for (int i = 0; i < 8; i++) { S += as[i]; SS += bs[i]; }
        float mu  = S * (1.0f / Dm);
        float var = SS * (1.0f / Dm) - mu * mu;
        s_mu  = mu;
        s_inv = rsqrtf(var + 1e-5f);
    }
    __syncthreads();
    float mu = s_mu, inv = s_inv;
    float4 g  = ((const float4*)gamma)[tid];
    float4 bb = ((const float4*)beta )[tid];
    int base = row * Dm + tid * 4;
    *(__half2*)&y[base]     = f22h((v.x - mu) * inv * g.x + bb.x,
                                   (v.y - mu) * inv * g.y + bb.y);
    *(__half2*)&y[base + 2] = f22h((v.z - mu) * inv * g.z + bb.z,
                                   (v.w - mu) * inv * g.w + bb.w);
}

// ---------------------------------------------------------------------------
// fp16 GEMM with bias: 128x256 block, BK=16, 8 warps of 64x64, cp.async.
// A fp16 [M][K], B fp16 [K][N]. Output fp32 (Cf) or fp16 (Ch).
// ---------------------------------------------------------------------------
#define G_ALD 24
#define G_BLD 264
#define G_AS (128*G_ALD)
#define G_BS (16*G_BLD)
#define GEMM_SMEM ((2*G_AS + 2*G_BS)*2)

__device__ __forceinline__ void gemm_body(const __half* __restrict__ A,
                                          const __half* __restrict__ B,
                                          const float* __restrict__ bias,
                                          float* __restrict__ Cf,
                                          __half* __restrict__ Ch,
                                          int M, int N, int K,
                                          __half* smem)
{
    __half* As = smem;                 // [2][128][24]
    __half* Bs = smem + 2 * G_AS;      // [2][16][264]

    int tid  = threadIdx.x;
    int lane = tid & 31, wid = tid >> 5;
    int wm = (wid & 1) * 64, wn = (wid >> 1) * 64;
    int l4 = lane >> 2, lk = lane & 3;
    int mb = blockIdx.y * 128, nb = blockIdx.x * 256;

    unsigned as_base = (unsigned)__cvta_generic_to_shared(As);
    unsigned bs_base = (unsigned)__cvta_generic_to_shared(Bs);

    int ar = tid >> 1, ach = tid & 1;      // A: 1 chunk/thread
    const __half* Ap = A + (size_t)(mb + ar) * K + ach * 8;

    float c[4][8][4];
    #pragma unroll
    for (int mi = 0; mi < 4; mi++)
        #pragma unroll
        for (int nj = 0; nj < 8; nj++)
            #pragma unroll
            for (int q = 0; q < 4; q++) c[mi][nj][q] = 0.f;

    #define G_LOAD(T, BUF)                                                     \
        do {                                                                   \
            cpasync16(as_base + (unsigned)((BUF) * G_AS + ar * G_ALD + ach * 8) * 2, \
                      Ap + (size_t)(T) * 16);                                  \
            _Pragma("unroll")                                                  \
            for (int u_ = 0; u_ < 2; u_++) {                                   \
                int lin_ = tid + u_ * 256;                                     \
                int kr_ = lin_ >> 5, ch_ = lin_ & 31;                          \
                cpasync16(bs_base + (unsigned)((BUF) * G_BS + kr_ * G_BLD + ch_ * 8) * 2, \
                          B + (size_t)((T) * 16 + kr_) * N + nb + ch_ * 8);    \
            }                                                                  \
        } while (0)

    G_LOAD(0, 0); CP_COMMIT();

    int nt = K >> 4;
    for (int t = 0; t < nt; t++) {
        int cur = t & 1, nxt = cur ^ 1;
        CP_WAIT0();
        __syncthreads();
        if (t + 1 < nt) { G_LOAD(t + 1, nxt); CP_COMMIT(); }

        const __half* Ab = As + cur * G_AS;
        const __half* Bb = Bs + cur * G_BS;

        unsigned af[4][4];
        #pragma unroll
        for (int mi = 0; mi < 4; mi++)
            ldsmx4(af[mi], a_frag_addr(Ab, lane, wm + mi * 16, G_ALD));
        #pragma unroll
        for (int g = 0; g < 4; g++) {
            unsigned bfr[4];
            ldsmx4t(bfr, bt_frag_addr(Bb, lane, 0, wn + g * 16, G_BLD));
            #pragma unroll
            for (int mi = 0; mi < 4; mi++) {
                MMA_F16(c[mi][2*g],   af[mi], bfr[0], bfr[1]);
                MMA_F16(c[mi][2*g+1], af[mi], bfr[2], bfr[3]);
            }
        }
    }
    #undef G_LOAD

    #pragma unroll
    for (int nj = 0; nj < 8; nj++) {
        int col = nb + wn + nj * 8 + 2 * lk;
        float2 bj = *(const float2*)&bias[col];
        #pragma unroll
        for (int mi = 0; mi < 4; mi++) {
            int r0 = mb + wm + mi * 16 + l4;
            float v0 = c[mi][nj][0] + bj.x, v1 = c[mi][nj][1] + bj.y;
            float v2 = c[mi][nj][2] + bj.x, v3 = c[mi][nj][3] + bj.y;
            if (Ch) {
                *(__half2*)&Ch[(size_t)r0 * N + col] = f22h(v0, v1);
                *(__half2*)&Ch[(size_t)(r0 + 8) * N + col] = f22h(v2, v3);
            } else {
                float2 o0; o0.x = v0; o0.y = v1;
                float2 o1; o1.x = v2; o1.y = v3;
                *(float2*)&Cf[(size_t)r0 * N + col] = o0;
                *(float2*)&Cf[(size_t)(r0 + 8) * N + col] = o1;
            }
        }
    }
}

__global__ void __launch_bounds__(256, 1)
gemm_f16(const __half* __restrict__ A, const __half* __restrict__ B,
         const float* __restrict__ bias, float* __restrict__ Cf,
         __half* __restrict__ Ch, int M, int N, int K)
{
    extern __shared__ __half smh[];
    gemm_body(A, B, bias, Cf, Ch, M, N, K, smh);
}

__global__ void __launch_bounds__(256, 1)
gemm_f16_kv(const __half* __restrict__ Ak, const __half* __restrict__ Av,
            const __half* __restrict__ Wk, const __half* __restrict__ Wv,
            const float* __restrict__ bk_, const float* __restrict__ bv_,
            __half* __restrict__ Ck, __half* __restrict__ Cv,
            int M, int N, int K)
{
    extern __shared__ __half smh[];
    if (blockIdx.z == 0) gemm_body(Ak, Wk, bk_, nullptr, Ck, M, N, K, smh);
    else                 gemm_body(Av, Wv, bv_, nullptr, Cv, M, N, K, smh);
}

// ---------------------------------------------------------------------------
// RoPE on fp16 buffers, in place.
// ---------------------------------------------------------------------------
__global__ void rope_kernel(__half* __restrict__ X, int heads, int total_pairs)
{
    int p = blockIdx.x * blockDim.x + threadIdx.x;
    if (p >= total_pairs) return;
    int i = p & 31;
    int t = (p / (32 * heads)) & (Sq - 1);
    float invf = exp2f(-13.287712379549449f * ((float)i * (1.0f / 32.0f)));
    float ang  = (float)t * invf;
    float sn, cs;
    sincosf(ang, &sn, &cs);
    __half2* xp = (__half2*)X + p;
    float2 v = __half22float2(*xp);
    *xp = f22h(v.x * cs - v.y * sn, v.x * sn + v.y * cs);
}

// ---------------------------------------------------------------------------
// Attention: FA2 layout. 8 warps x 16 q-rows, full 128-key tiles per warp.
// Stats in registers (quad shfl only). P stays in registers (S-frag -> A-frag).
// Two sweeps; cp.async double-buffered K, async V.
// ---------------------------------------------------------------------------
#define A_LD 72
#define A_TS (128*A_LD)
#define ATTN_SMEM (4*A_TS*2)

__global__ void __launch_bounds__(256, 1)
attn_kernel(const int* __restrict__ lens, float* __restrict__ attn)
{
    extern __shared__ __half smh[];
    __half* Qs  = smh;
    __half* Ks0 = Qs + A_TS;
    __half* Ks1 = Ks0 + A_TS;
    __half* Vs  = Ks1 + A_TS;

    int tid  = threadIdx.x;
    int lane = tid & 31, wid = tid >> 5;
    int wm = wid * 16;
    int l4 = lane >> 2, lk = lane & 3;

    int mt = (int)gridDim.x - 1 - (int)blockIdx.x;   // heavy-first
    int qh = blockIdx.y, b = blockIdx.z;
    int kvh = qh >> 2;
    int grp = qh & 3;
    int len = lens[b];

    unsigned qs_addr = (unsigned)__cvta_generic_to_shared(Qs);
    unsigned ks_addr[2] = {
        (unsigned)__cvta_generic_to_shared(Ks0),
        (unsigned)__cvta_generic_to_shared(Ks1)
    };
    unsigned vs_addr = (unsigned)__cvta_generic_to_shared(Vs);

    // async Q load (128 rows x 8 chunks of 16B)
    #pragma unroll
    for (int i = 0; i < 4; i++) {
        int lin = tid + i * 256;
        int r = lin >> 3, ch = lin & 7;
        cpasync16(qs_addr + (unsigned)(r * A_LD + ch * 8) * 2,
                  &g_Qh[((size_t)(b * Sq + mt * 128 + r)) * (NQ * DQh) + qh * 64 + ch * 8]);
    }

    unsigned q_ptr = a_frag_addr(Qs, lane, wm, A_LD);
    unsigned k_ptr[2][8], v_ptr[4];
    #pragma unroll
    for (int g = 0; g < 8; g++) {
        k_ptr[0][g] = bn_frag_addr(Ks0, lane, g * 16, A_LD);
        k_ptr[1][g] = bn_frag_addr(Ks1, lane, g * 16, A_LD);
    }
    #pragma unroll
    for (int g = 0; g < 4; g++)
        v_ptr[g] = bt_frag_addr(Vs, lane, 0, g * 16, A_LD);

    int jend = min(mt, (len - 1) >> 7);
    size_t attn_head = (((size_t)(b * GRP + grp)) * NKV + kvh) * Sq;

    #define LOAD_K_ASYNC(JT, BUFADDR)                                           \
        do {                                                                    \
            _Pragma("unroll")                                                   \
            for (int i_ = 0; i_ < 4; i_++) {                                    \
                int lin_ = tid + i_ * 256;                                      \
                int r_ = lin_ >> 3, ch_ = lin_ & 7;                             \
                cpasync16((BUFADDR) + (unsigned)(r_ * A_LD + ch_ * 8) * 2,      \
                    &g_Kh[((size_t)(b * Sq + (JT) * 128 + r_)) * (NKV * DQh)    \
                          + kvh * 64 + ch_ * 8]);                               \
            }                                                                   \
        } while (0)
    #define LOAD_V_ASYNC(JT)                                                    \
        do {                                                                    \
            _Pragma("unroll")                                                   \
            for (int i_ = 0; i_ < 4; i_++) {                                    \
                int lin_ = tid + i_ * 256;                                      \
                int r_ = lin_ >> 3, ch_ = lin_ & 7;                             \
                cpasync16(vs_addr + (unsigned)(r_ * A_LD + ch_ * 8) * 2,        \
                    &g_Vh[((size_t)(b * Sq + (JT) * 128 + r_)) * (NKV * DQh)    \
                          + kvh * 64 + ch_ * 8]);                               \
            }                                                                   \
        } while (0)

    // QK^T: warp tile 16m x 128n (16 n8-tiles), d loop of 4 k16 steps
    #define QK_MMA(KBUF)                                                        \
        do {                                                                    \
            _Pragma("unroll")                                                   \
            for (int kk = 0; kk < 4; kk++) {                                    \
                unsigned af[4];                                                 \
                ldsmx4(af, q_ptr + kk * 32);                                    \
                _Pragma("unroll")                                               \
                for (int g = 0; g < 8; g++) {                                   \
                    unsigned bfr[4];                                            \
                    ldsmx4(bfr, k_ptr[KBUF][g] + kk * 32);                      \
                    MMA_F16(s[2*g],   af, bfr[0], bfr[1]);                      \
                    MMA_F16(s[2*g+1], af, bfr[2], bfr[3]);                      \
                }                                                               \
            }                                                                   \
        } while (0)

    float rm0 = -3.0e38f, rm1 = -3.0e38f, rl0 = 0.f, rl1 = 0.f;
    int qr0 = mt * 128 + wm + l4, qr1 = qr0 + 8;

    // =================== Sweep 1: stats (registers only) ===================
    LOAD_K_ASYNC(0, ks_addr[0]); CP_COMMIT();
    for (int jt = 0; jt <= jend; jt++) {
        CP_WAIT0();
        __syncthreads();
        int kb = jt & 1;
        if (jt < jend) { LOAD_K_ASYNC(jt + 1, ks_addr[(jt + 1) & 1]); CP_COMMIT(); }

        float s[16][4];
        #pragma unroll
        for (int nj = 0; nj < 16; nj++)
            #pragma unroll
            for (int q = 0; q < 4; q++) s[nj][q] = 0.f;
        QK_MMA(kb);

        // scale + mask
        #pragma unroll
        for (int nj = 0; nj < 16; nj++) {
            int kc0 = jt * 128 + nj * 8 + 2 * lk, kc1 = kc0 + 1;
            s[nj][0] = (kc0 > qr0 || kc0 >= len) ? -1.0e30f : s[nj][0] * 0.125f;
            s[nj][1] = (kc1 > qr0 || kc1 >= len) ? -1.0e30f : s[nj][1] * 0.125f;
            s[nj][2] = (kc0 > qr1 || kc0 >= len) ? -1.0e30f : s[nj][2] * 0.125f;
            s[nj][3] = (kc1 > qr1 || kc1 >= len) ? -1.0e30f : s[nj][3] * 0.125f;
        }

        // tile row max + exp-sum via quad shfl
        float m0 = -3.0e38f, m1 = -3.0e38f;
        #pragma unroll
        for (int nj = 0; nj < 16; nj++) {
            m0 = fmaxf(m0, fmaxf(s[nj][0], s[nj][1]));
            m1 = fmaxf(m1, fmaxf(s[nj][2], s[nj][3]));
        }
        m0 = fmaxf(m0, __shfl_xor_sync(0xffffffffu, m0, 1));
        m0 = fmaxf(m0, __shfl_xor_sync(0xffffffffu, m0, 2));
        m1 = fmaxf(m1, __shfl_xor_sync(0xffffffffu, m1, 1));
        m1 = fmaxf(m1, __shfl_xor_sync(0xffffffffu, m1, 2));
        float s0 = 0.f, s1 = 0.f;
        #pragma unroll
        for (int nj = 0; nj < 16; nj++) {
            s0 += __expf(s[nj][0] - m0) + __expf(s[nj][1] - m0);
            s1 += __expf(s[nj][2] - m1) + __expf(s[nj][3] - m1);
        }
        s0 += __shfl_xor_sync(0xffffffffu, s0, 1);
        s0 += __shfl_xor_sync(0xffffffffu, s0, 2);
        s1 += __shfl_xor_sync(0xffffffffu, s1, 1);
        s1 += __shfl_xor_sync(0xffffffffu, s1, 2);

        // merge running stats
        float n0 = fmaxf(rm0, m0);
        rl0 = rl0 * __expf(rm0 - n0) + s0 * __expf(m0 - n0);
        rm0 = n0;
        float n1 = fmaxf(rm1, m1);
        rl1 = rl1 * __expf(rm1 - n1) + s1 * __expf(m1 - n1);
        rm1 = n1;
    }
    __syncthreads();   // protect K buffers before sweep 2 reload

    float il0 = 1.0f / rl0, il1 = 1.0f / rl1;

    float o[8][4];
    #pragma unroll
    for (int dj = 0; dj < 8; dj++)
        #pragma unroll
        for (int q = 0; q < 4; q++) o[dj][q] = 0.f;

    // =================== Sweep 2: probs + PV ===================
    LOAD_K_ASYNC(0, ks_addr[0]); CP_COMMIT();
    for (int jt = 0; jt <= jend; jt++) {
        CP_WAIT0();
        __syncthreads();
        int kb = jt & 1;
        LOAD_V_ASYNC(jt); CP_COMMIT();
        bool more = (jt < jend);
        if (more) { LOAD_K_ASYNC(jt + 1, ks_addr[(jt + 1) & 1]); CP_COMMIT(); }

        float s[16][4];
        #pragma unroll
        for (int nj = 0; nj < 16; nj++)
            #pragma unroll
            for (int q = 0; q < 4; q++) s[nj][q] = 0.f;
        QK_MMA(kb);

        // final probs (masked -> 0), write gmem, keep in regs
        #pragma unroll
        for (int nj = 0; nj < 16; nj++) {
            int kc0 = jt * 128 + nj * 8 + 2 * lk, kc1 = kc0 + 1;
            float p0 = (kc0 > qr0 || kc0 >= len) ? 0.f
                     : __expf(s[nj][0] * 0.125f - rm0) * il0;
            float p1 = (kc1 > qr0 || kc1 >= len) ? 0.f
                     : __expf(s[nj][1] * 0.125f - rm0) * il0;
            float p2 = (kc0 > qr1 || kc0 >= len) ? 0.f
                     : __expf(s[nj][2] * 0.125f - rm1) * il1;
            float p3 = (kc1 > qr1 || kc1 >= len) ? 0.f
                     : __expf(s[nj][3] * 0.125f - rm1) * il1;
            float2 w0; w0.x = p0; w0.y = p1;
            float2 w1; w1.x = p2; w1.y = p3;
            *(float2*)&attn[(attn_head + qr0) * Sq + kc0] = w0;
            *(float2*)&attn[(attn_head + qr1) * Sq + kc0] = w1;
            s[nj][0] = p0; s[nj][1] = p1; s[nj][2] = p2; s[nj][3] = p3;
        }

        // wait for V (K prefetch may remain in flight)
        if (more) { CP_WAIT1(); } else { CP_WAIT0(); }
        __syncthreads();

        // O += P @ V : P A-frags built from S accumulator frags (FA2)
        #pragma unroll
        for (int kk = 0; kk < 8; kk++) {
            unsigned af[4];
            af[0] = pack_h2(s[2*kk][0],   s[2*kk][1]);
            af[1] = pack_h2(s[2*kk][2],   s[2*kk][3]);
            af[2] = pack_h2(s[2*kk+1][0], s[2*kk+1][1]);
            af[3] = pack_h2(s[2*kk+1][2], s[2*kk+1][3]);
            #pragma unroll
            for (int g = 0; g < 4; g++) {
                unsigned bfr[4];
                ldsmx4t(bfr, v_ptr[g] + kk * 16 * A_LD * 2);
                MMA_F16(o[2*g],   af, bfr[0], bfr[1]);
                MMA_F16(o[2*g+1], af, bfr[2], bfr[3]);
            }
        }
    }

    // zero-fill fully masked tiles
    for (int jt = jend + 1; jt < Sq / 128; jt++) {
        float4 z = make_float4(0.f, 0.f, 0.f, 0.f);
        #pragma unroll
        for (int i = 0; i < 16; i++) {
            int lin = tid + i * 256;
            int r = lin >> 5, c4 = (lin & 31) * 4;
            *(float4*)&attn[(attn_head + mt * 128 + r) * Sq + jt * 128 + c4] = z;
        }
    }

    // epilogue: write O (fp16)
    {
        int gr0 = b * Sq + qr0;   // qr0 = mt*128 + wm + l4
        #pragma unroll
        for (int dj = 0; dj < 8; dj++) {
            int col = qh * 64 + dj * 8 + 2 * lk;
            *(__half2*)&g_Oh[(size_t)gr0 * (NQ * DVh) + col] = f22h(o[dj][0], o[dj][1]);
            *(__half2*)&g_Oh[(size_t)(gr0 + 8) * (NQ * DVh) + col] = f22h(o[dj][2], o[dj][3]);
        }
    }
    #undef LOAD_K_ASYNC
    #undef LOAD_V_ASYNC
    #undef QK_MMA
}

// ---------------------------------------------------------------------------
// Launch
// ---------------------------------------------------------------------------
extern "C" void kernel_launch(void* const* d_in, const int* in_sizes, int n_in,
                              void* d_out, int out_size)
{
    const float* x_q  = (const float*)d_in[0];
    const float* x_k  = (const float*)d_in[1];
    const float* x_v  = (const float*)d_in[2];
    const int*   lens = (const int*)  d_in[3];
    const float* gam  = (const float*)d_in[4];
    const float* bet  = (const float*)d_in[5];
    const float* Wq   = (const float*)d_in[6];
    const float* bq   = (const float*)d_in[7];
    const float* Wk   = (const float*)d_in[8];
    const float* bk   = (const float*)d_in[9];
    const float* Wv   = (const float*)d_in[10];
    const float* bv   = (const float*)d_in[11];
    const float* Wo   = (const float*)d_in[12];
    const float* bo   = (const float*)d_in[13];

    float* out  = (float*)d_out;                       // (B, S, 1024)
    float* attn = out + (size_t)Bq * Sq * Dm;          // (B, GRP, NKV, S, S)

    __half *xnq, *xnk, *xnv, *Qh, *Kh, *Vh, *Oh;
    __half *Wqh, *Wkh, *Wvh, *Woh;
    cudaGetSymbolAddress((void**)&xnq, g_xnq);
    cudaGetSymbolAddress((void**)&xnk, g_xnk);
    cudaGetSymbolAddress((void**)&xnv, g_xnv);
    cudaGetSymbolAddress((void**)&Qh,  g_Qh);
    cudaGetSymbolAddress((void**)&Kh,  g_Kh);
    cudaGetSymbolAddress((void**)&Vh,  g_Vh);
    cudaGetSymbolAddress((void**)&Oh,  g_Oh);
    cudaGetSymbolAddress((void**)&Wqh, g_Wqh);
    cudaGetSymbolAddress((void**)&Wkh, g_Wkh);
    cudaGetSymbolAddress((void**)&Wvh, g_Wvh);
    cudaGetSymbolAddress((void**)&Woh, g_Woh);

    const int M = Bq * Sq;   // 4096

    static bool attr_set = false;
    if (!attr_set) {
        cudaFuncSetAttribute(gemm_f16, cudaFuncAttributeMaxDynamicSharedMemorySize, GEMM_SMEM);
        cudaFuncSetAttribute(gemm_f16_kv, cudaFuncAttributeMaxDynamicSharedMemorySize, GEMM_SMEM);
        cudaFuncSetAttribute(attn_kernel, cudaFuncAttributeMaxDynamicSharedMemorySize, ATTN_SMEM);
        attr_set = true;
    }

    // 0) Weights -> fp16
    w2h_kernel<<<dim3((Dm * Dm / 4 + 255) / 256, 4), 256>>>(
        Wq, Wo, Wk, Wv, Wqh, Woh, Wkh, Wvh);

    // 1) LayerNorms (fused, fp16 out)
    ln3_kernel<<<dim3(M, 3), 256>>>(x_q, x_k, x_v, gam, bet, xnq, xnk, xnv);

    // 2) Projections (all-fp16 GEMMs)
    gemm_f16<<<dim3(Dm / 256, M / 128), 256, GEMM_SMEM>>>(xnq, Wqh, bq, nullptr, Qh, M, NQ * DQh, Dm);
    gemm_f16_kv<<<dim3(1, M / 128, 2), 256, GEMM_SMEM>>>(
        xnk, xnv, Wkh, Wvh, bk, bv, Kh, Vh, M, NKV * DQh, Dm);

    // 3) RoPE on fp16 Q/K
    {
        int pq = Bq * Sq * NQ * 32;
        int pk = Bq * Sq * NKV * 32;
        rope_kernel<<<(pq + 255) / 256, 256>>>(Qh, NQ, pq);
        rope_kernel<<<(pk + 255) / 256, 256>>>(Kh, NKV, pk);
    }

    // 4) Attention (FA2 layout, two sweeps)
    attn_kernel<<<dim3(Sq / 128, NQ, Bq), 256, ATTN_SMEM>>>(lens, attn);

    // 5) Output projection (fp16 A, fp32 out)
    gemm_f16<<<dim3(Dm / 256, M / 128), 256, GEMM_SMEM>>>(Oh, Woh, bo, out, nullptr, M, Dm, Dm);
}

// round 10
// speedup vs baseline: 1.1831x; 1.1831x over previous
#include <cuda_runtime.h>
#include <cuda_fp16.h>
#include <cmath>

// Problem constants
#define Bq     2
#define Sq     2048
#define Dm     1024
#define NQ     16
#define NKV    4
#define GRP    4
#define DQh    64
#define DVh    64

// Scratch (device globals — no allocation allowed)
__device__ __align__(16) __half g_xnq[Bq*Sq*Dm];
__device__ __align__(16) __half g_xnk[Bq*Sq*Dm];
__device__ __align__(16) __half g_xnv[Bq*Sq*Dm];
__device__ __align__(16) __half g_Wqh[Dm*NQ*DQh];
__device__ __align__(16) __half g_Wkh[Dm*NKV*DQh];
__device__ __align__(16) __half g_Wvh[Dm*NKV*DVh];
__device__ __align__(16) __half g_Woh[NQ*DVh*Dm];
__device__ __align__(16) __half g_Qh[Bq*Sq*NQ*DQh];
__device__ __align__(16) __half g_Kh[Bq*Sq*NKV*DQh];
__device__ __align__(16) __half g_Vh[Bq*Sq*NKV*DVh];
__device__ __align__(16) __half g_Oh[Bq*Sq*NQ*DVh];

// fp16 mma: m16n8k16, f32 accum
#define MMA_F16(c, a, b0, b1)                                                  \
    asm volatile("mma.sync.aligned.m16n8k16.row.col.f32.f16.f16.f32 "          \
                 "{%0,%1,%2,%3},{%4,%5,%6,%7},{%8,%9},{%0,%1,%2,%3};"          \
                 : "+f"((c)[0]), "+f"((c)[1]), "+f"((c)[2]), "+f"((c)[3])      \
                 : "r"((a)[0]), "r"((a)[1]), "r"((a)[2]), "r"((a)[3]),         \
                   "r"(b0), "r"(b1))

__device__ __forceinline__ void ldsmx4(unsigned r[4], unsigned saddr) {
    asm volatile("ldmatrix.sync.aligned.m8n8.x4.shared.b16 {%0,%1,%2,%3}, [%4];"
                 : "=r"(r[0]), "=r"(r[1]), "=r"(r[2]), "=r"(r[3])
                 : "r"(saddr));
}
__device__ __forceinline__ void ldsmx4t(unsigned r[4], unsigned saddr) {
    asm volatile("ldmatrix.sync.aligned.m8n8.x4.trans.shared.b16 {%0,%1,%2,%3}, [%4];"
                 : "=r"(r[0]), "=r"(r[1]), "=r"(r[2]), "=r"(r[3])
                 : "r"(saddr));
}

// A-operand (row-major m16 x k16) ldmatrix lane address; add kk*32 bytes per k16 step
__device__ __forceinline__ unsigned a_frag_addr(const __half* base, int lane,
                                                int r0, int ldm) {
    const __half* p = base + (size_t)(r0 + (lane & 7) + ((lane >> 3) & 1) * 8) * ldm
                           + ((lane >> 4) & 1) * 8;
    return (unsigned)__cvta_generic_to_shared(p);
}
// B-operand, source [n][k] (k contiguous): non-trans ldmatrix (n16 x k16)
__device__ __forceinline__ unsigned bn_frag_addr(const __half* base, int lane,
                                                 int n0, int ldm) {
    const __half* p = base + (size_t)(n0 + (lane & 7) + ((lane >> 4) & 1) * 8) * ldm
                           + ((lane >> 3) & 1) * 8;
    return (unsigned)__cvta_generic_to_shared(p);
}
// B-operand, source [k][n] (n contiguous): trans ldmatrix (k16 x n16)
__device__ __forceinline__ unsigned bt_frag_addr(const __half* base, int lane,
                                                 int k0, int n0, int ldm) {
    const __half* p = base + (size_t)(k0 + (lane & 7) + ((lane >> 3) & 1) * 8) * ldm
                           + n0 + ((lane >> 4) & 1) * 8;
    return (unsigned)__cvta_generic_to_shared(p);
}

__device__ __forceinline__ void cpasync16(unsigned dst, const void* src) {
    asm volatile("cp.async.cg.shared.global [%0], [%1], 16;" :: "r"(dst), "l"(src));
}
#define CP_COMMIT() asm volatile("cp.async.commit_group;")
#define CP_WAIT0()  asm volatile("cp.async.wait_group 0;")
#define CP_WAIT1()  asm volatile("cp.async.wait_group 1;")

__device__ __forceinline__ __half2 f22h(float a, float b) {
    return __floats2half2_rn(a, b);
}
__device__ __forceinline__ unsigned pack_h2(float a, float b) {
    __half2 h = __floats2half2_rn(a, b);
    return *(unsigned*)&h;
}

// ---------------------------------------------------------------------------
// Weight conversion fp32 -> fp16
// ---------------------------------------------------------------------------
__global__ void w2h_kernel(const float* __restrict__ Wq, const float* __restrict__ Wo,
                           const float* __restrict__ Wk, const float* __restrict__ Wv,
                           __half* q, __half* o_, __half* k, __half* v)
{
    int which = blockIdx.y;
    const float* src = (which == 0) ? Wq : (which == 1) ? Wo : (which == 2) ? Wk : Wv;
    __half* dst      = (which == 0) ? q  : (which == 1) ? o_ : (which == 2) ? k  : v;
    int n = (which < 2) ? Dm * Dm : Dm * NKV * DQh;
    int i = (blockIdx.x * blockDim.x + threadIdx.x) * 4;
    if (i < n) {
        float4 w = *(const float4*)&src[i];
        *(__half2*)&dst[i]     = f22h(w.x, w.y);
        *(__half2*)&dst[i + 2] = f22h(w.z, w.w);
    }
}

// ---------------------------------------------------------------------------
// Fused LayerNorm x3 (fp16 output)
// ---------------------------------------------------------------------------
__global__ void ln3_kernel(const float* __restrict__ xq,
                           const float* __restrict__ xk,
                           const float* __restrict__ xv,
                           const float* __restrict__ gamma,
                           const float* __restrict__ beta,
                           __half* __restrict__ yq,
                           __half* __restrict__ yk,
                           __half* __restrict__ yv)
{
    int row = blockIdx.x;
    int which = blockIdx.y;
    const float* x = (which == 0) ? xq : (which == 1) ? xk : xv;
    __half* y      = (which == 0) ? yq : (which == 1) ? yk : yv;
    int tid = threadIdx.x;
    const float4* xr = (const float4*)(x + (size_t)row * Dm);
    float4 v = xr[tid];
    float s  = v.x + v.y + v.z + v.w;
    float ss = v.x*v.x + v.y*v.y + v.z*v.z + v.w*v.w;
    #pragma unroll
    for (int o = 16; o > 0; o >>= 1) {
        s  += __shfl_down_sync(0xffffffffu, s,  o);
        ss += __shfl_down_sync(0xffffffffu, ss, o);
    }
    __shared__ float as[8], bs[8];
    __shared__ float s_mu, s_inv;
    if ((tid & 31) == 0) { as[tid >> 5] = s; bs[tid >> 5] = ss; }
    __syncthreads();
    if (tid == 0) {
        float S = 0.f, SS = 0.f;
        #pragma unroll
        for (int i = 0; i < 8; i++) { S += as[i]; SS += bs[i]; }
        float mu  = S * (1.0f / Dm);
        float var = SS * (1.0f / Dm) - mu * mu;
        s_mu  = mu;
        s_inv = rsqrtf(var + 1e-5f);
    }
    __syncthreads();
    float mu = s_mu, inv = s_inv;
    float4 g  = ((const float4*)gamma)[tid];
    float4 bb = ((const float4*)beta )[tid];
    int base = row * Dm + tid * 4;
    *(__half2*)&y[base]     = f22h((v.x - mu) * inv * g.x + bb.x,
                                   (v.y - mu) * inv * g.y + bb.y);
    *(__half2*)&y[base + 2] = f22h((v.z - mu) * inv * g.z + bb.z,
                                   (v.w - mu) * inv * g.w + bb.w);
}

// ---------------------------------------------------------------------------
// fp16 GEMM with bias: 128x128 block, BK=32, 8 warps of 64x32, cp.async,
// 2 CTAs/SM. A fp16 [M][K], B fp16 [K][N]. Output fp32 (Cf) or fp16 (Ch).
// ---------------------------------------------------------------------------
#define G_ALD 40
#define G_BLD 136
#define G_AS (128*G_ALD)
#define G_BS (32*G_BLD)
#define GEMM_SMEM ((2*G_AS + 2*G_BS)*2)

__device__ __forceinline__ void gemm_body(const __half* __restrict__ A,
                                          const __half* __restrict__ B,
                                          const float* __restrict__ bias,
                                          float* __restrict__ Cf,
                                          __half* __restrict__ Ch,
                                          int N, int K,
                                          int mblk, int nblk,
                                          __half* smem)
{
    __half* As = smem;                 // [2][128][40]
    __half* Bs = smem + 2 * G_AS;      // [2][32][136]

    int tid  = threadIdx.x;
    int lane = tid & 31, wid = tid >> 5;
    int wm = (wid & 1) * 64, wn = (wid >> 1) * 32;
    int l4 = lane >> 2, lk = lane & 3;
    int mb = mblk * 128, nb = nblk * 128;

    unsigned as_base = (unsigned)__cvta_generic_to_shared(As);
    unsigned bs_base = (unsigned)__cvta_generic_to_shared(Bs);

    int ar = tid >> 1, ach = (tid & 1) * 2;  // A: 2 chunks of 8 halves / thread
    const __half* Ap = A + (size_t)(mb + ar) * K + ach * 8;

    float c[4][4][4];
    #pragma unroll
    for (int mi = 0; mi < 4; mi++)
        #pragma unroll
        for (int nj = 0; nj < 4; nj++)
            #pragma unroll
            for (int q = 0; q < 4; q++) c[mi][nj][q] = 0.f;

    #define G_LOAD(T, BUF)                                                     \
        do {                                                                   \
            cpasync16(as_base + (unsigned)((BUF) * G_AS + ar * G_ALD + ach * 8) * 2, \
                      Ap + (size_t)(T) * 32);                                  \
            cpasync16(as_base + (unsigned)((BUF) * G_AS + ar * G_ALD + ach * 8 + 8) * 2, \
                      Ap + (size_t)(T) * 32 + 8);                              \
            _Pragma("unroll")                                                  \
            for (int u_ = 0; u_ < 2; u_++) {                                   \
                int lin_ = tid + u_ * 256;                                     \
                int kr_ = lin_ >> 4, ch_ = lin_ & 15;                          \
                cpasync16(bs_base + (unsigned)((BUF) * G_BS + kr_ * G_BLD + ch_ * 8) * 2, \
                          B + (size_t)((T) * 32 + kr_) * N + nb + ch_ * 8);    \
            }                                                                  \
        } while (0)

    G_LOAD(0, 0); CP_COMMIT();

    int nt = K >> 5;
    for (int t = 0; t < nt; t++) {
        int cur = t & 1, nxt = cur ^ 1;
        CP_WAIT0();
        __syncthreads();
        if (t + 1 < nt) { G_LOAD(t + 1, nxt); CP_COMMIT(); }

        const __half* Ab = As + cur * G_AS;
        const __half* Bb = Bs + cur * G_BS;

        #pragma unroll
        for (int kk = 0; kk < 2; kk++) {
            unsigned af[4][4];
            #pragma unroll
            for (int mi = 0; mi < 4; mi++)
                ldsmx4(af[mi], a_frag_addr(Ab, lane, wm + mi * 16, G_ALD) + kk * 32);
            #pragma unroll
            for (int g = 0; g < 2; g++) {
                unsigned bfr[4];
                ldsmx4t(bfr, bt_frag_addr(Bb, lane, kk * 16, wn + g * 16, G_BLD));
                #pragma unroll
                for (int mi = 0; mi < 4; mi++) {
                    MMA_F16(c[mi][2*g],   af[mi], bfr[0], bfr[1]);
                    MMA_F16(c[mi][2*g+1], af[mi], bfr[2], bfr[3]);
                }
            }
        }
    }
    #undef G_LOAD

    #pragma unroll
    for (int nj = 0; nj < 4; nj++) {
        int col = nb + wn + nj * 8 + 2 * lk;
        float2 bj = *(const float2*)&bias[col];
        #pragma unroll
        for (int mi = 0; mi < 4; mi++) {
            int r0 = mb + wm + mi * 16 + l4;
            float v0 = c[mi][nj][0] + bj.x, v1 = c[mi][nj][1] + bj.y;
            float v2 = c[mi][nj][2] + bj.x, v3 = c[mi][nj][3] + bj.y;
            if (Ch) {
                *(__half2*)&Ch[(size_t)r0 * N + col] = f22h(v0, v1);
                *(__half2*)&Ch[(size_t)(r0 + 8) * N + col] = f22h(v2, v3);
            } else {
                float2 o0; o0.x = v0; o0.y = v1;
                float2 o1; o1.x = v2; o1.y = v3;
                *(float2*)&Cf[(size_t)r0 * N + col] = o0;
                *(float2*)&Cf[(size_t)(r0 + 8) * N + col] = o1;
            }
        }
    }
}

// Fused Q+K+V projections: 384 CTAs (256 Q, 64 K, 64 V)
__global__ void __launch_bounds__(256, 2)
gemm_qkv(const __half* __restrict__ Aq, const __half* __restrict__ Ak,
         const __half* __restrict__ Av,
         const __half* __restrict__ Wq, const __half* __restrict__ Wk,
         const __half* __restrict__ Wv,
         const float* __restrict__ bq_, const float* __restrict__ bk_,
         const float* __restrict__ bv_,
         __half* __restrict__ Cq, __half* __restrict__ Ck,
         __half* __restrict__ Cv)
{
    extern __shared__ __half smh[];
    int bx = blockIdx.x;
    if (bx < 256) {
        gemm_body(Aq, Wq, bq_, nullptr, Cq, NQ * DQh, Dm, bx >> 3, bx & 7, smh);
    } else if (bx < 320) {
        int i = bx - 256;
        gemm_body(Ak, Wk, bk_, nullptr, Ck, NKV * DQh, Dm, i >> 1, i & 1, smh);
    } else {
        int i = bx - 320;
        gemm_body(Av, Wv, bv_, nullptr, Cv, NKV * DVh, Dm, i >> 1, i & 1, smh);
    }
}

// Output projection: 256 CTAs
__global__ void __launch_bounds__(256, 2)
gemm_o(const __half* __restrict__ A, const __half* __restrict__ B,
       const float* __restrict__ bias, float* __restrict__ Cf)
{
    extern __shared__ __half smh[];
    int bx = blockIdx.x;
    gemm_body(A, B, bias, Cf, nullptr, Dm, Dm, bx >> 3, bx & 7, smh);
}

// ---------------------------------------------------------------------------
// RoPE on fp16 Q and K in one launch.
// ---------------------------------------------------------------------------
__global__ void rope_kernel(__half* __restrict__ Xq, __half* __restrict__ Xk,
                            int pq, int total)
{
    int p = blockIdx.x * blockDim.x + threadIdx.x;
    if (p >= total) return;
    __half2* xp;
    int i, t;
    if (p < pq) {
        i = p & 31;
        t = (p / (32 * NQ)) & (Sq - 1);
        xp = (__half2*)Xq + p;
    } else {
        int pk = p - pq;
        i = pk & 31;
        t = (pk / (32 * NKV)) & (Sq - 1);
        xp = (__half2*)Xk + pk;
    }
    float invf = exp2f(-13.287712379549449f * ((float)i * (1.0f / 32.0f)));
    float ang  = (float)t * invf;
    float sn, cs;
    sincosf(ang, &sn, &cs);
    float2 v = __half22float2(*xp);
    *xp = f22h(v.x * cs - v.y * sn, v.x * sn + v.y * cs);
}

// ---------------------------------------------------------------------------
// Attention: FA2 layout. 8 warps x 16 q-rows, full 128-key tiles per warp.
// Stats in registers; P stays in registers (S-frag -> A-frag). Two sweeps.
// ---------------------------------------------------------------------------
#define A_LD 72
#define A_TS (128*A_LD)
#define ATTN_SMEM (4*A_TS*2)

__global__ void __launch_bounds__(256, 1)
attn_kernel(const int* __restrict__ lens, float* __restrict__ attn)
{
    extern __shared__ __half smh[];
    __half* Qs  = smh;
    __half* Ks0 = Qs + A_TS;
    __half* Ks1 = Ks0 + A_TS;
    __half* Vs  = Ks1 + A_TS;

    int tid  = threadIdx.x;
    int lane = tid & 31, wid = tid >> 5;
    int wm = wid * 16;
    int l4 = lane >> 2, lk = lane & 3;

    int mt = (int)gridDim.x - 1 - (int)blockIdx.x;   // heavy-first
    int qh = blockIdx.y, b = blockIdx.z;
    int kvh = qh >> 2;
    int grp = qh & 3;
    int len = lens[b];

    unsigned qs_addr = (unsigned)__cvta_generic_to_shared(Qs);
    unsigned ks_addr[2] = {
        (unsigned)__cvta_generic_to_shared(Ks0),
        (unsigned)__cvta_generic_to_shared(Ks1)
    };
    unsigned vs_addr = (unsigned)__cvta_generic_to_shared(Vs);

    // async Q load
    #pragma unroll
    for (int i = 0; i < 4; i++) {
        int lin = tid + i * 256;
        int r = lin >> 3, ch = lin & 7;
        cpasync16(qs_addr + (unsigned)(r * A_LD + ch * 8) * 2,
                  &g_Qh[((size_t)(b * Sq + mt * 128 + r)) * (NQ * DQh) + qh * 64 + ch * 8]);
    }

    unsigned q_ptr = a_frag_addr(Qs, lane, wm, A_LD);
    unsigned k_ptr[2][8], v_ptr[4];
    #pragma unroll
    for (int g = 0; g < 8; g++) {
        k_ptr[0][g] = bn_frag_addr(Ks0, lane, g * 16, A_LD);
        k_ptr[1][g] = bn_frag_addr(Ks1, lane, g * 16, A_LD);
    }
    #pragma unroll
    for (int g = 0; g < 4; g++)
        v_ptr[g] = bt_frag_addr(Vs, lane, 0, g * 16, A_LD);

    int jend = min(mt, (len - 1) >> 7);
    size_t attn_head = (((size_t)(b * GRP + grp)) * NKV + kvh) * Sq;

    #define LOAD_K_ASYNC(JT, BUFADDR)                                           \
        do {                                                                    \
            _Pragma("unroll")                                                   \
            for (int i_ = 0; i_ < 4; i_++) {                                    \
                int lin_ = tid + i_ * 256;                                      \
                int r_ = lin_ >> 3, ch_ = lin_ & 7;                             \
                cpasync16((BUFADDR) + (unsigned)(r_ * A_LD + ch_ * 8) * 2,      \
                    &g_Kh[((size_t)(b * Sq + (JT) * 128 + r_)) * (NKV * DQh)    \
                          + kvh * 64 + ch_ * 8]);                               \
            }                                                                   \
        } while (0)
    #define LOAD_V_ASYNC(JT)                                                    \
        do {                                                                    \
            _Pragma("unroll")                                                   \
            for (int i_ = 0; i_ < 4; i_++) {                                    \
                int lin_ = tid + i_ * 256;                                      \
                int r_ = lin_ >> 3, ch_ = lin_ & 7;                             \
                cpasync16(vs_addr + (unsigned)(r_ * A_LD + ch_ * 8) * 2,        \
                    &g_Vh[((size_t)(b * Sq + (JT) * 128 + r_)) * (NKV * DQh)    \
                          + kvh * 64 + ch_ * 8]);                               \
            }                                                                   \
        } while (0)

    #define QK_MMA(KBUF)                                                        \
        do {                                                                    \
            _Pragma("unroll")                                                   \
            for (int kk = 0; kk < 4; kk++) {                                    \
                unsigned af[4];                                                 \
                ldsmx4(af, q_ptr + kk * 32);                                    \
                _Pragma("unroll")                                               \
                for (int g = 0; g < 8; g++) {                                   \
                    unsigned bfr[4];                                            \
                    ldsmx4(bfr, k_ptr[KBUF][g] + kk * 32);                      \
                    MMA_F16(s[2*g],   af, bfr[0], bfr[1]);                      \
                    MMA_F16(s[2*g+1], af, bfr[2], bfr[3]);                      \
                }                                                               \
            }                                                                   \
        } while (0)

    float rm0 = -3.0e38f, rm1 = -3.0e38f, rl0 = 0.f, rl1 = 0.f;
    int qr0 = mt * 128 + wm + l4, qr1 = qr0 + 8;

    // =================== Sweep 1: stats (registers only) ===================
    LOAD_K_ASYNC(0, ks_addr[0]); CP_COMMIT();
    for (int jt = 0; jt <= jend; jt++) {
        CP_WAIT0();
        __syncthreads();
        int kb = jt & 1;
        if (jt < jend) { LOAD_K_ASYNC(jt + 1, ks_addr[(jt + 1) & 1]); CP_COMMIT(); }

        float s[16][4];
        #pragma unroll
        for (int nj = 0; nj < 16; nj++)
            #pragma unroll
            for (int q = 0; q < 4; q++) s[nj][q] = 0.f;
        QK_MMA(kb);

        #pragma unroll
        for (int nj = 0; nj < 16; nj++) {
            int kc0 = jt * 128 + nj * 8 + 2 * lk, kc1 = kc0 + 1;
            s[nj][0] = (kc0 > qr0 || kc0 >= len) ? -1.0e30f : s[nj][0] * 0.125f;
            s[nj][1] = (kc1 > qr0 || kc1 >= len) ? -1.0e30f : s[nj][1] * 0.125f;
            s[nj][2] = (kc0 > qr1 || kc0 >= len) ? -1.0e30f : s[nj][2] * 0.125f;
            s[nj][3] = (kc1 > qr1 || kc1 >= len) ? -1.0e30f : s[nj][3] * 0.125f;
        }

        float m0 = -3.0e38f, m1 = -3.0e38f;
        #pragma unroll
        for (int nj = 0; nj < 16; nj++) {
            m0 = fmaxf(m0, fmaxf(s[nj][0], s[nj][1]));
            m1 = fmaxf(m1, fmaxf(s[nj][2], s[nj][3]));
        }
        m0 = fmaxf(m0, __shfl_xor_sync(0xffffffffu, m0, 1));
        m0 = fmaxf(m0, __shfl_xor_sync(0xffffffffu, m0, 2));
        m1 = fmaxf(m1, __shfl_xor_sync(0xffffffffu, m1, 1));
        m1 = fmaxf(m1, __shfl_xor_sync(0xffffffffu, m1, 2));
        float s0 = 0.f, s1 = 0.f;
        #pragma unroll
        for (int nj = 0; nj < 16; nj++) {
            s0 += __expf(s[nj][0] - m0) + __expf(s[nj][1] - m0);
            s1 += __expf(s[nj][2] - m1) + __expf(s[nj][3] - m1);
        }
        s0 += __shfl_xor_sync(0xffffffffu, s0, 1);
        s0 += __shfl_xor_sync(0xffffffffu, s0, 2);
        s1 += __shfl_xor_sync(0xffffffffu, s1, 1);
        s1 += __shfl_xor_sync(0xffffffffu, s1, 2);

        float n0 = fmaxf(rm0, m0);
        rl0 = rl0 * __expf(rm0 - n0) + s0 * __expf(m0 - n0);
        rm0 = n0;
        float n1 = fmaxf(rm1, m1);
        rl1 = rl1 * __expf(rm1 - n1) + s1 * __expf(m1 - n1);
        rm1 = n1;
    }
    __syncthreads();

    float il0 = 1.0f / rl0, il1 = 1.0f / rl1;

    float o[8][4];
    #pragma unroll
    for (int dj = 0; dj < 8; dj++)
        #pragma unroll
        for (int q = 0; q < 4; q++) o[dj][q] = 0.f;

    // =================== Sweep 2: probs + PV ===================
    LOAD_K_ASYNC(0, ks_addr[0]); CP_COMMIT();
    for (int jt = 0; jt <= jend; jt++) {
        CP_WAIT0();
        __syncthreads();
        int kb = jt & 1;
        LOAD_V_ASYNC(jt); CP_COMMIT();
        bool more = (jt < jend);
        if (more) { LOAD_K_ASYNC(jt + 1, ks_addr[(jt + 1) & 1]); CP_COMMIT(); }

        float s[16][4];
        #pragma unroll
        for (int nj = 0; nj < 16; nj++)
            #pragma unroll
            for (int q = 0; q < 4; q++) s[nj][q] = 0.f;
        QK_MMA(kb);

        #pragma unroll
        for (int nj = 0; nj < 16; nj++) {
            int kc0 = jt * 128 + nj * 8 + 2 * lk, kc1 = kc0 + 1;
            float p0 = (kc0 > qr0 || kc0 >= len) ? 0.f
                     : __expf(s[nj][0] * 0.125f - rm0) * il0;
            float p1 = (kc1 > qr0 || kc1 >= len) ? 0.f
                     : __expf(s[nj][1] * 0.125f - rm0) * il0;
            float p2 = (kc0 > qr1 || kc0 >= len) ? 0.f
                     : __expf(s[nj][2] * 0.125f - rm1) * il1;
            float p3 = (kc1 > qr1 || kc1 >= len) ? 0.f
                     : __expf(s[nj][3] * 0.125f - rm1) * il1;
            float2 w0; w0.x = p0; w0.y = p1;
            float2 w1; w1.x = p2; w1.y = p3;
            *(float2*)&attn[(attn_head + qr0) * Sq + kc0] = w0;
            *(float2*)&attn[(attn_head + qr1) * Sq + kc0] = w1;
            s[nj][0] = p0; s[nj][1] = p1; s[nj][2] = p2; s[nj][3] = p3;
        }

        if (more) { CP_WAIT1(); } else { CP_WAIT0(); }
        __syncthreads();

        #pragma unroll
        for (int kk = 0; kk < 8; kk++) {
            unsigned af[4];
            af[0] = pack_h2(s[2*kk][0],   s[2*kk][1]);
            af[1] = pack_h2(s[2*kk][2],   s[2*kk][3]);
            af[2] = pack_h2(s[2*kk+1][0], s[2*kk+1][1]);
            af[3] = pack_h2(s[2*kk+1][2], s[2*kk+1][3]);
            #pragma unroll
            for (int g = 0; g < 4; g++) {
                unsigned bfr[4];
                ldsmx4t(bfr, v_ptr[g] + kk * 16 * A_LD * 2);
                MMA_F16(o[2*g],   af, bfr[0], bfr[1]);
                MMA_F16(o[2*g+1], af, bfr[2], bfr[3]);
            }
        }
    }

    // zero-fill fully masked tiles
    for (int jt = jend + 1; jt < Sq / 128; jt++) {
        float4 z = make_float4(0.f, 0.f, 0.f, 0.f);
        #pragma unroll
        for (int i = 0; i < 16; i++) {
            int lin = tid + i * 256;
            int r = lin >> 5, c4 = (lin & 31) * 4;
            *(float4*)&attn[(attn_head + mt * 128 + r) * Sq + jt * 128 + c4] = z;
        }
    }

    // epilogue: write O (fp16)
    {
        int gr0 = b * Sq + qr0;
        #pragma unroll
        for (int dj = 0; dj < 8; dj++) {
            int col = qh * 64 + dj * 8 + 2 * lk;
            *(__half2*)&g_Oh[(size_t)gr0 * (NQ * DVh) + col] = f22h(o[dj][0], o[dj][1]);
            *(__half2*)&g_Oh[(size_t)(gr0 + 8) * (NQ * DVh) + col] = f22h(o[dj][2], o[dj][3]);
        }
    }
    #undef LOAD_K_ASYNC
    #undef LOAD_V_ASYNC
    #undef QK_MMA
}

// ---------------------------------------------------------------------------
// Launch
// ---------------------------------------------------------------------------
extern "C" void kernel_launch(void* const* d_in, const int* in_sizes, int n_in,
                              void* d_out, int out_size)
{
    const float* x_q  = (const float*)d_in[0];
    const float* x_k  = (const float*)d_in[1];
    const float* x_v  = (const float*)d_in[2];
    const int*   lens = (const int*)  d_in[3];
    const float* gam  = (const float*)d_in[4];
    const float* bet  = (const float*)d_in[5];
    const float* Wq   = (const float*)d_in[6];
    const float* bq   = (const float*)d_in[7];
    const float* Wk   = (const float*)d_in[8];
    const float* bk   = (const float*)d_in[9];
    const float* Wv   = (const float*)d_in[10];
    const float* bv   = (const float*)d_in[11];
    const float* Wo   = (const float*)d_in[12];
    const float* bo   = (const float*)d_in[13];

    float* out  = (float*)d_out;                       // (B, S, 1024)
    float* attn = out + (size_t)Bq * Sq * Dm;          // (B, GRP, NKV, S, S)

    __half *xnq, *xnk, *xnv, *Qh, *Kh, *Vh, *Oh;
    __half *Wqh, *Wkh, *Wvh, *Woh;
    cudaGetSymbolAddress((void**)&xnq, g_xnq);
    cudaGetSymbolAddress((void**)&xnk, g_xnk);
    cudaGetSymbolAddress((void**)&xnv, g_xnv);
    cudaGetSymbolAddress((void**)&Qh,  g_Qh);
    cudaGetSymbolAddress((void**)&Kh,  g_Kh);
    cudaGetSymbolAddress((void**)&Vh,  g_Vh);
    cudaGetSymbolAddress((void**)&Oh,  g_Oh);
    cudaGetSymbolAddress((void**)&Wqh, g_Wqh);
    cudaGetSymbolAddress((void**)&Wkh, g_Wkh);
    cudaGetSymbolAddress((void**)&Wvh, g_Wvh);
    cudaGetSymbolAddress((void**)&Woh, g_Woh);

    const int M = Bq * Sq;   // 4096

    static bool attr_set = false;
    if (!attr_set) {
        cudaFuncSetAttribute(gemm_qkv, cudaFuncAttributeMaxDynamicSharedMemorySize, GEMM_SMEM);
        cudaFuncSetAttribute(gemm_o, cudaFuncAttributeMaxDynamicSharedMemorySize, GEMM_SMEM);
        cudaFuncSetAttribute(attn_kernel, cudaFuncAttributeMaxDynamicSharedMemorySize, ATTN_SMEM);
        attr_set = true;
    }

    // 0) Weights -> fp16
    w2h_kernel<<<dim3((Dm * Dm / 4 + 255) / 256, 4), 256>>>(
        Wq, Wo, Wk, Wv, Wqh, Woh, Wkh, Wvh);

    // 1) LayerNorms (fused, fp16 out)
    ln3_kernel<<<dim3(M, 3), 256>>>(x_q, x_k, x_v, gam, bet, xnq, xnk, xnv);

    // 2) Q+K+V projections in ONE launch (384 CTAs)
    gemm_qkv<<<384, 256, GEMM_SMEM>>>(xnq, xnk, xnv, Wqh, Wkh, Wvh,
                                      bq, bk, bv, Qh, Kh, Vh);

    // 3) RoPE (Q and K fused)
    {
        int pq = Bq * Sq * NQ * 32;
        int pk = Bq * Sq * NKV * 32;
        rope_kernel<<<(pq + pk + 255) / 256, 256>>>(Qh, Kh, pq, pq + pk);
    }

    // 4) Attention (FA2 layout, two sweeps)
    attn_kernel<<<dim3(Sq / 128, NQ, Bq), 256, ATTN_SMEM>>>(lens, attn);

    // 5) Output projection (256 CTAs)
    gemm_o<<<256, 256, GEMM_SMEM>>>(Oh, Woh, bo, out);
}